// round 4
// baseline (speedup 1.0000x reference)
#include <cuda_runtime.h>
#include <cstdint>

__device__ float g_X[25165824];     // [m=(n,l,c)][v]
__device__ float g_A[3145728];      // rounded a0,a1,a2
__device__ float g_Asq[3145728];    // rounded squares
__device__ float g_P[176160768];    // planes [cc][n][l][w], cc 0..223
__device__ float g_O[50331648];     // [m=(n,l,w)][o]
__device__ float g_Wt[14336];       // [k][o]

__device__ __forceinline__ float rna(float x){
  unsigned u; asm("cvt.rna.tf32.f32 %0, %1;" : "=r"(u) : "f"(x));
  return __uint_as_float(u);
}
__device__ __forceinline__ void cp16(float* s, const float* g){
  unsigned sa = (unsigned)__cvta_generic_to_shared(s);
  asm volatile("cp.async.cg.shared.global [%0], [%1], 16;\n" :: "r"(sa), "l"(g));
}
__device__ __forceinline__ void cpcommit(){ asm volatile("cp.async.commit_group;\n"); }
__device__ __forceinline__ void cpwait(){ asm volatile("cp.async.wait_group 0;\n"); }
__device__ __forceinline__ void mma8(float* d, const unsigned* a, const unsigned* b){
  asm volatile("mma.sync.aligned.m16n8k8.row.col.f32.tf32.tf32.f32 "
    "{%0,%1,%2,%3},{%4,%5,%6,%7},{%8,%9},{%0,%1,%2,%3};\n"
    : "+f"(d[0]), "+f"(d[1]), "+f"(d[2]), "+f"(d[3])
    : "r"(a[0]), "r"(a[1]), "r"(a[2]), "r"(a[3]), "r"(b[0]), "r"(b[1]));
}

__global__ void pack_a_k(const float* __restrict__ a0, const float* __restrict__ a1,
                         const float* __restrict__ a2){
  int i = blockIdx.x * 1024 + threadIdx.x;
  int z = i >> 20;
  const float* s = (z == 0) ? a0 : ((z == 1) ? a1 : a2);
  g_A[i] = rna(s[i & 1048575]);
}
__global__ void pack_w_k(const float* __restrict__ W){
  int i = blockIdx.x * 256 + threadIdx.x;
  if (i < 14336){ int k = i >> 6, o = i & 63; g_Wt[i] = rna(W[o * 224 + k]); }
}
// x[n][c][v][l] -> g_X[(n*12+l)*32+c][v] and plane c: g_P[c][n][l][v]
__global__ void pack_x_k(const float* __restrict__ x){
  __shared__ float sm[6656];
  int nc = blockIdx.x >> 1, h = blockIdx.x & 1, t = threadIdx.x;
  int n = nc >> 5, c = nc & 31;
  const float* src = x + (size_t)nc * 12288 + h * 6144;
  for (int i = t; i < 6144; i += 256) sm[(i / 12) * 13 + (i % 12)] = src[i];
  __syncthreads();
  for (int l = 0; l < 12; l++){
    float* d1 = g_X + ((size_t)((n * 12 + l) * 32 + c)) * 1024 + h * 512;
    float* d2 = g_P + ((size_t)((c * 64 + n) * 12 + l)) * 1024 + h * 512;
    for (int v = t; v < 512; v += 256){ float r = rna(sm[v * 13 + l]); d1[v] = r; d2[v] = r; }
  }
}

// K=1024 tf32 GEMM, 128x128x16 tiles. mode0: Asq=A@A grid(8,8,3). mode1: Y grid(48,192)
__global__ __launch_bounds__(256, 2) void gemm_k(int mode){
  __shared__ float sm[9472]; // As[2][128*20] | Bs[2][16*136]
  const int t = threadIdx.x, lane = t & 31, wid = t >> 5;
  const int bx = blockIdx.x, by = blockIdx.y, bz = blockIdx.z;
  const float *Ap, *Bp; float* Cp = nullptr; int kb = 0, w0 = 0;
  if (mode == 0){
    size_t zo = (size_t)bz << 20;
    Ap = g_A + zo + (size_t)by * 131072;
    Bp = g_A + zo + bx * 128;
    Cp = g_Asq + zo + (size_t)by * 131072 + bx * 128;
  } else {
    Ap = g_X + (size_t)by * 131072;
    kb = bx >> 3; w0 = (bx & 7) * 128;
    Bp = ((kb & 1) ? g_Asq : g_A) + ((size_t)(kb >> 1) << 20) + w0;
  }
  const int ar = t >> 2, aq = t & 3, br = t >> 5, bq = t & 31;
  float acc[4][4][4];
  #pragma unroll
  for (int i = 0; i < 4; i++) for (int j = 0; j < 4; j++) for (int q = 0; q < 4; q++) acc[i][j][q] = 0.f;
  { float* As = sm; float* Bs = sm + 5120;
    cp16(As + ar * 20 + aq * 4,        Ap + (size_t)ar * 1024 + aq * 4);
    cp16(As + (ar + 64) * 20 + aq * 4, Ap + (size_t)(ar + 64) * 1024 + aq * 4);
    cp16(Bs + br * 136 + bq * 4,       Bp + (size_t)br * 1024 + bq * 4);
    cp16(Bs + (br + 8) * 136 + bq * 4, Bp + (size_t)(br + 8) * 1024 + bq * 4);
    cpcommit(); }
  const int wm = wid >> 2, wn = wid & 3, arow = wm * 64, bcol = wn * 32;
  for (int kt = 0; kt < 64; kt++){
    int cur = kt & 1;
    cpwait(); __syncthreads();
    if (kt < 63){
      float* As = sm + (cur ^ 1) * 2560; float* Bs = sm + 5120 + (cur ^ 1) * 2176;
      const float* Ag = Ap + (kt + 1) * 16;
      const float* Bg = Bp + (size_t)(kt + 1) * 16384;
      cp16(As + ar * 20 + aq * 4,        Ag + (size_t)ar * 1024 + aq * 4);
      cp16(As + (ar + 64) * 20 + aq * 4, Ag + (size_t)(ar + 64) * 1024 + aq * 4);
      cp16(Bs + br * 136 + bq * 4,       Bg + (size_t)br * 1024 + bq * 4);
      cp16(Bs + (br + 8) * 136 + bq * 4, Bg + (size_t)(br + 8) * 1024 + bq * 4);
      cpcommit();
    }
    const float* As = sm + cur * 2560; const float* Bs = sm + 5120 + cur * 2176;
    #pragma unroll
    for (int ks = 0; ks < 2; ks++){
      unsigned af[4][4], bf[4][2];
      int kk = ks * 8 + (lane & 3), rr = lane >> 2;
      #pragma unroll
      for (int mf = 0; mf < 4; mf++){
        int r = arow + mf * 16 + rr;
        af[mf][0] = __float_as_uint(As[r * 20 + kk]);
        af[mf][1] = __float_as_uint(As[(r + 8) * 20 + kk]);
        af[mf][2] = __float_as_uint(As[r * 20 + kk + 4]);
        af[mf][3] = __float_as_uint(As[(r + 8) * 20 + kk + 4]);
      }
      #pragma unroll
      for (int nf = 0; nf < 4; nf++){
        int cc = bcol + nf * 8 + rr;
        bf[nf][0] = __float_as_uint(Bs[kk * 136 + cc]);
        bf[nf][1] = __float_as_uint(Bs[(kk + 4) * 136 + cc]);
      }
      #pragma unroll
      for (int mf = 0; mf < 4; mf++) for (int nf = 0; nf < 4; nf++) mma8(acc[mf][nf], af[mf], bf[nf]);
    }
    __syncthreads();
  }
  if (mode == 0){
    #pragma unroll
    for (int mf = 0; mf < 4; mf++){
      int r = arow + mf * 16 + (lane >> 2);
      #pragma unroll
      for (int nf = 0; nf < 4; nf++){
        int cc = bcol + nf * 8 + (lane & 3) * 2;
        Cp[(size_t)r * 1024 + cc]           = rna(acc[mf][nf][0]);
        Cp[(size_t)r * 1024 + cc + 1]       = rna(acc[mf][nf][1]);
        Cp[(size_t)(r + 8) * 1024 + cc]     = rna(acc[mf][nf][2]);
        Cp[(size_t)(r + 8) * 1024 + cc + 1] = rna(acc[mf][nf][3]);
      }
    }
  } else {
    for (int ph = 0; ph < 2; ph++){
      __syncthreads();
      if (wm == ph){
        #pragma unroll
        for (int mf = 0; mf < 4; mf++){
          int r = mf * 16 + (lane >> 2);
          #pragma unroll
          for (int nf = 0; nf < 4; nf++){
            int cc = bcol + nf * 8 + (lane & 3) * 2;
            sm[r * 136 + cc]           = rna(acc[mf][nf][0]);
            sm[r * 136 + cc + 1]       = rna(acc[mf][nf][1]);
            sm[(r + 8) * 136 + cc]     = rna(acc[mf][nf][2]);
            sm[(r + 8) * 136 + cc + 1] = rna(acc[mf][nf][3]);
          }
        }
      }
      __syncthreads();
      int m0 = by * 128 + ph * 64;
      #pragma unroll
      for (int i = 0; i < 8; i++){
        int e = t + i * 256, rr = e >> 5, q = e & 31;
        int m = m0 + rr, n = m / 384, rem = m % 384, l = rem >> 5, c = rem & 31;
        int p = 32 + kb * 32 + c;
        float4 v = *(const float4*)&sm[rr * 136 + q * 4];
        *(float4*)(g_P + ((size_t)((p * 64 + n) * 12 + l)) * 1024 + w0 + q * 4) = v;
      }
    }
  }
}

// stage 3: O[m][o] = sum_k P[k][m]*Wt[k][o] + b[o], tiles 128m x 64o, K=224
__global__ __launch_bounds__(256) void gemm3_k(const float* __restrict__ bias){
  __shared__ float As[1088], Ws[512]; // As[8][136], Ws[8][64]
  const int t = threadIdx.x, lane = t & 31, wid = t >> 5;
  const size_t m0 = (size_t)blockIdx.x * 128;
  const int wm = wid >> 1, wn = wid & 1;
  float acc[2][4][4];
  #pragma unroll
  for (int i = 0; i < 2; i++) for (int j = 0; j < 4; j++) for (int q = 0; q < 4; q++) acc[i][j][q] = 0.f;
  for (int kt = 0; kt < 28; kt++){
    __syncthreads();
    { int r = t >> 5, q = t & 31;
      *(float4*)&As[r * 136 + q * 4] = *(const float4*)(g_P + (size_t)(kt * 8 + r) * 786432 + m0 + q * 4);
      if (t < 128) *(float4*)&Ws[(t >> 4) * 64 + (t & 15) * 4] = *(const float4*)(g_Wt + (kt * 8 + (t >> 4)) * 64 + (t & 15) * 4);
    }
    __syncthreads();
    unsigned af[2][4], bf[4][2];
    int k = lane & 3, rr = lane >> 2;
    #pragma unroll
    for (int mf = 0; mf < 2; mf++){
      int r = wm * 32 + mf * 16 + rr;
      af[mf][0] = __float_as_uint(As[k * 136 + r]);
      af[mf][1] = __float_as_uint(As[k * 136 + r + 8]);
      af[mf][2] = __float_as_uint(As[(k + 4) * 136 + r]);
      af[mf][3] = __float_as_uint(As[(k + 4) * 136 + r + 8]);
    }
    #pragma unroll
    for (int nf = 0; nf < 4; nf++){
      int n0 = wn * 32 + nf * 8 + rr;
      bf[nf][0] = __float_as_uint(Ws[k * 64 + n0]);
      bf[nf][1] = __float_as_uint(Ws[(k + 4) * 64 + n0]);
    }
    #pragma unroll
    for (int mf = 0; mf < 2; mf++) for (int nf = 0; nf < 4; nf++) mma8(acc[mf][nf], af[mf], bf[nf]);
  }
  #pragma unroll
  for (int mf = 0; mf < 2; mf++){
    size_t r = m0 + wm * 32 + mf * 16 + (lane >> 2);
    #pragma unroll
    for (int nf = 0; nf < 4; nf++){
      int o = wn * 32 + nf * 8 + (lane & 3) * 2;
      float b0 = __ldg(bias + o), b1 = __ldg(bias + o + 1);
      g_O[r * 64 + o]           = acc[mf][nf][0] + b0;
      g_O[r * 64 + o + 1]       = acc[mf][nf][1] + b1;
      g_O[(r + 8) * 64 + o]     = acc[mf][nf][2] + b0;
      g_O[(r + 8) * 64 + o + 1] = acc[mf][nf][3] + b1;
    }
  }
}

// O[(n,l,w)][o] -> out[n][o][w][l]
__global__ void trans_k(float* __restrict__ out){
  __shared__ float sm[6144]; // [l][w(8)][o]
  int w0 = blockIdx.x * 8, n = blockIdx.y, t = threadIdx.x;
  for (int e = t; e < 6144; e += 256){
    int l = e / 512, rem = e % 512, w = rem >> 6, o = rem & 63;
    sm[e] = g_O[((size_t)(n * 12 + l) * 1024 + w0 + w) * 64 + o];
  }
  __syncthreads();
  for (int e = t; e < 6144; e += 256){
    int o = e / 96, rem = e % 96, w = rem / 12, l = rem % 12;
    out[((size_t)(n * 64 + o) * 1024 + w0 + w) * 12 + l] = sm[(l * 8 + w) * 64 + o];
  }
}

extern "C" void kernel_launch(void* const* d_in, const int* in_sizes, int n_in,
                              void* d_out, int out_size) {
  const float* x  = (const float*)d_in[0];
  const float* a0 = (const float*)d_in[1];
  const float* a1 = (const float*)d_in[2];
  const float* a2 = (const float*)d_in[3];
  const float* W  = (const float*)d_in[4];
  const float* b  = (const float*)d_in[5];
  float* out = (float*)d_out;
  pack_a_k<<<3072, 1024>>>(a0, a1, a2);
  pack_w_k<<<56, 256>>>(W);
  pack_x_k<<<4096, 256>>>(x);
  gemm_k<<<dim3(8, 8, 3), 256>>>(0);
  gemm_k<<<dim3(48, 192, 1), 256>>>(1);
  gemm3_k<<<6144, 256>>>(b);
  trans_k<<<dim3(128, 64), 256>>>(out);
}

// round 6
// speedup vs baseline: 1.0583x; 1.0583x over previous
#include <cuda_runtime.h>
#include <cstdint>

__device__ float g_X[25165824];     // [m=(n,l,c)][v]
__device__ float g_A[3145728];      // rounded a0,a1,a2
__device__ float g_Asq[3145728];    // rounded squares
__device__ float g_P[176160768];    // planes [cc][n][l][w], cc 0..223
__device__ float g_O[50331648];     // [m=(n,l,w)][o]
__device__ float g_Wt[14336];       // [k][o]

__device__ __forceinline__ float rna(float x){
  unsigned u; asm("cvt.rna.tf32.f32 %0, %1;" : "=r"(u) : "f"(x));
  return __uint_as_float(u);
}
__device__ __forceinline__ void cp16(float* s, const float* g){
  unsigned sa = (unsigned)__cvta_generic_to_shared(s);
  asm volatile("cp.async.cg.shared.global [%0], [%1], 16;\n" :: "r"(sa), "l"(g));
}
__device__ __forceinline__ void cpcommit(){ asm volatile("cp.async.commit_group;\n"); }
__device__ __forceinline__ void cpwait(){ asm volatile("cp.async.wait_group 0;\n"); }
__device__ __forceinline__ void mma8(float* d, const unsigned* a, const unsigned* b){
  asm volatile("mma.sync.aligned.m16n8k8.row.col.f32.tf32.tf32.f32 "
    "{%0,%1,%2,%3},{%4,%5,%6,%7},{%8,%9},{%0,%1,%2,%3};\n"
    : "+f"(d[0]), "+f"(d[1]), "+f"(d[2]), "+f"(d[3])
    : "r"(a[0]), "r"(a[1]), "r"(a[2]), "r"(a[3]), "r"(b[0]), "r"(b[1]));
}

__global__ void pack_a_k(const float* __restrict__ a0, const float* __restrict__ a1,
                         const float* __restrict__ a2){
  int i = blockIdx.x * 1024 + threadIdx.x;
  int z = i >> 20;
  const float* s = (z == 0) ? a0 : ((z == 1) ? a1 : a2);
  g_A[i] = rna(s[i & 1048575]);
}
__global__ void pack_w_k(const float* __restrict__ W){
  int i = blockIdx.x * 256 + threadIdx.x;
  if (i < 14336){ int k = i >> 6, o = i & 63; g_Wt[i] = rna(W[o * 224 + k]); }
}
// x[n][c][v][l] -> g_X[(n*12+l)*32+c][v] and plane c: g_P[c][n][l][v]
__global__ void pack_x_k(const float* __restrict__ x){
  __shared__ float sm[6656];
  int nc = blockIdx.x >> 1, h = blockIdx.x & 1, t = threadIdx.x;
  int n = nc >> 5, c = nc & 31;
  const float* src = x + (size_t)nc * 12288 + h * 6144;
  for (int i = t; i < 6144; i += 256) sm[(i / 12) * 13 + (i % 12)] = src[i];
  __syncthreads();
  for (int l = 0; l < 12; l++){
    float* d1 = g_X + ((size_t)((n * 12 + l) * 32 + c)) * 1024 + h * 512;
    float* d2 = g_P + ((size_t)((c * 64 + n) * 12 + l)) * 1024 + h * 512;
    for (int v = t; v < 512; v += 256){ float r = rna(sm[v * 13 + l]); d1[v] = r; d2[v] = r; }
  }
}

// K=1024 tf32 GEMM, 128x128 tile, KTILE=32, 2 buffers, 1 barrier/iter.
// smem layout (floats): A[2][128*36] at 0, B[2][32*136] at 9216. total 17920 fl = 71680 B
#define GSMEM 71680
__global__ __launch_bounds__(256, 2) void gemm_k(int mode){
  extern __shared__ float sm[];
  const int t = threadIdx.x, lane = t & 31, wid = t >> 5;
  const int bx = blockIdx.x, by = blockIdx.y, bz = blockIdx.z;
  const float *Ap, *Bp; float* Cp = nullptr; int kb = 0, w0 = 0;
  if (mode == 0){
    size_t zo = (size_t)bz << 20;
    Ap = g_A + zo + (size_t)by * 131072;
    Bp = g_A + zo + bx * 128;
    Cp = g_Asq + zo + (size_t)by * 131072 + bx * 128;
  } else {
    Ap = g_X + (size_t)by * 131072;
    kb = bx >> 3; w0 = (bx & 7) * 128;
    Bp = ((kb & 1) ? g_Asq : g_A) + ((size_t)(kb >> 1) << 20) + w0;
  }
  // loaders: A tile 128x32 (1024 quads): row=idx>>3, q=idx&7
  //          B tile 32x128 (1024 quads): row=idx>>5, q=idx&31
  float acc[4][4][4];
  #pragma unroll
  for (int i = 0; i < 4; i++) for (int j = 0; j < 4; j++) for (int q = 0; q < 4; q++) acc[i][j][q] = 0.f;
  { // prologue: buffer 0
    float* As = sm; float* Bs = sm + 9216;
    #pragma unroll
    for (int i = 0; i < 4; i++){
      int idx = t + i * 256; int r = idx >> 3, q = idx & 7;
      cp16(As + r * 36 + q * 4, Ap + (size_t)r * 1024 + q * 4);
    }
    #pragma unroll
    for (int i = 0; i < 4; i++){
      int idx = t + i * 256; int r = idx >> 5, q = idx & 31;
      cp16(Bs + r * 136 + q * 4, Bp + (size_t)r * 1024 + q * 4);
    }
    cpcommit();
  }
  const int wm = wid >> 2, wn = wid & 3, arow = wm * 64, bcol = wn * 32;
  for (int kt = 0; kt < 32; kt++){
    int b = kt & 1;
    cpwait();
    __syncthreads();
    if (kt < 31){
      float* As = sm + (b ^ 1) * 4608; float* Bs = sm + 9216 + (b ^ 1) * 4352;
      const float* Ag = Ap + (kt + 1) * 32;
      const float* Bg = Bp + (size_t)(kt + 1) * 32768;
      #pragma unroll
      for (int i = 0; i < 4; i++){
        int idx = t + i * 256; int r = idx >> 3, q = idx & 7;
        cp16(As + r * 36 + q * 4, Ag + (size_t)r * 1024 + q * 4);
      }
      #pragma unroll
      for (int i = 0; i < 4; i++){
        int idx = t + i * 256; int r = idx >> 5, q = idx & 31;
        cp16(Bs + r * 136 + q * 4, Bg + (size_t)r * 1024 + q * 4);
      }
      cpcommit();
    } else {
      cpcommit(); // empty group so final cpwait() semantics stay uniform
    }
    const float* As = sm + b * 4608; const float* Bs = sm + 9216 + b * 4352;
    #pragma unroll
    for (int ks = 0; ks < 4; ks++){
      unsigned af[4][4], bf[4][2];
      int kk = ks * 8 + (lane & 3), rr = lane >> 2;
      #pragma unroll
      for (int mf = 0; mf < 4; mf++){
        int r = arow + mf * 16 + rr;
        af[mf][0] = __float_as_uint(As[r * 36 + kk]);
        af[mf][1] = __float_as_uint(As[(r + 8) * 36 + kk]);
        af[mf][2] = __float_as_uint(As[r * 36 + kk + 4]);
        af[mf][3] = __float_as_uint(As[(r + 8) * 36 + kk + 4]);
      }
      #pragma unroll
      for (int nf = 0; nf < 4; nf++){
        int cc = bcol + nf * 8 + rr;
        bf[nf][0] = __float_as_uint(Bs[kk * 136 + cc]);
        bf[nf][1] = __float_as_uint(Bs[(kk + 4) * 136 + cc]);
      }
      #pragma unroll
      for (int mf = 0; mf < 4; mf++) for (int nf = 0; nf < 4; nf++) mma8(acc[mf][nf], af[mf], bf[nf]);
    }
  }
  cpwait();
  if (mode == 0){
    #pragma unroll
    for (int mf = 0; mf < 4; mf++){
      int r = arow + mf * 16 + (lane >> 2);
      #pragma unroll
      for (int nf = 0; nf < 4; nf++){
        int cc = bcol + nf * 8 + (lane & 3) * 2;
        Cp[(size_t)r * 1024 + cc]           = rna(acc[mf][nf][0]);
        Cp[(size_t)r * 1024 + cc + 1]       = rna(acc[mf][nf][1]);
        Cp[(size_t)(r + 8) * 1024 + cc]     = rna(acc[mf][nf][2]);
        Cp[(size_t)(r + 8) * 1024 + cc + 1] = rna(acc[mf][nf][3]);
      }
    }
  } else {
    for (int ph = 0; ph < 2; ph++){
      __syncthreads();
      if (wm == ph){
        #pragma unroll
        for (int mf = 0; mf < 4; mf++){
          int r = mf * 16 + (lane >> 2);
          #pragma unroll
          for (int nf = 0; nf < 4; nf++){
            int cc = bcol + nf * 8 + (lane & 3) * 2;
            sm[r * 136 + cc]           = rna(acc[mf][nf][0]);
            sm[r * 136 + cc + 1]       = rna(acc[mf][nf][1]);
            sm[(r + 8) * 136 + cc]     = rna(acc[mf][nf][2]);
            sm[(r + 8) * 136 + cc + 1] = rna(acc[mf][nf][3]);
          }
        }
      }
      __syncthreads();
      int m0 = by * 128 + ph * 64;
      #pragma unroll
      for (int i = 0; i < 8; i++){
        int e = t + i * 256, rr = e >> 5, q = e & 31;
        int m = m0 + rr, n = m / 384, rem = m % 384, l = rem >> 5, c = rem & 31;
        int p = 32 + kb * 32 + c;
        float4 v = *(const float4*)&sm[rr * 136 + q * 4];
        *(float4*)(g_P + ((size_t)((p * 64 + n) * 12 + l)) * 1024 + w0 + q * 4) = v;
      }
    }
  }
}

// stage 3: O[m][o] = sum_k P[k][m]*Wt[k][o] + b[o], tiles 128m x 64o, K=224
__global__ __launch_bounds__(256) void gemm3_k(const float* __restrict__ bias){
  __shared__ float As[1088], Ws[512];
  const int t = threadIdx.x, lane = t & 31, wid = t >> 5;
  const size_t m0 = (size_t)blockIdx.x * 128;
  const int wm = wid >> 1, wn = wid & 1;
  float acc[2][4][4];
  #pragma unroll
  for (int i = 0; i < 2; i++) for (int j = 0; j < 4; j++) for (int q = 0; q < 4; q++) acc[i][j][q] = 0.f;
  for (int kt = 0; kt < 28; kt++){
    __syncthreads();
    { int r = t >> 5, q = t & 31;
      *(float4*)&As[r * 136 + q * 4] = *(const float4*)(g_P + (size_t)(kt * 8 + r) * 786432 + m0 + q * 4);
      if (t < 128) *(float4*)&Ws[(t >> 4) * 64 + (t & 15) * 4] = *(const float4*)(g_Wt + (kt * 8 + (t >> 4)) * 64 + (t & 15) * 4);
    }
    __syncthreads();
    unsigned af[2][4], bf[4][2];
    int k = lane & 3, rr = lane >> 2;
    #pragma unroll
    for (int mf = 0; mf < 2; mf++){
      int r = wm * 32 + mf * 16 + rr;
      af[mf][0] = __float_as_uint(As[k * 136 + r]);
      af[mf][1] = __float_as_uint(As[k * 136 + r + 8]);
      af[mf][2] = __float_as_uint(As[(k + 4) * 136 + r]);
      af[mf][3] = __float_as_uint(As[(k + 4) * 136 + r + 8]);
    }
    #pragma unroll
    for (int nf = 0; nf < 4; nf++){
      int n0 = wn * 32 + nf * 8 + rr;
      bf[nf][0] = __float_as_uint(Ws[k * 64 + n0]);
      bf[nf][1] = __float_as_uint(Ws[(k + 4) * 64 + n0]);
    }
    #pragma unroll
    for (int mf = 0; mf < 2; mf++) for (int nf = 0; nf < 4; nf++) mma8(acc[mf][nf], af[mf], bf[nf]);
  }
  #pragma unroll
  for (int mf = 0; mf < 2; mf++){
    size_t r = m0 + wm * 32 + mf * 16 + (lane >> 2);
    #pragma unroll
    for (int nf = 0; nf < 4; nf++){
      int o = wn * 32 + nf * 8 + (lane & 3) * 2;
      float b0 = __ldg(bias + o), b1 = __ldg(bias + o + 1);
      g_O[r * 64 + o]           = acc[mf][nf][0] + b0;
      g_O[r * 64 + o + 1]       = acc[mf][nf][1] + b1;
      g_O[(r + 8) * 64 + o]     = acc[mf][nf][2] + b0;
      g_O[(r + 8) * 64 + o + 1] = acc[mf][nf][3] + b1;
    }
  }
}

// O[(n,l,w)][o] -> out[n][o][w][l]
__global__ void trans_k(float* __restrict__ out){
  __shared__ float sm[6144];
  int w0 = blockIdx.x * 8, n = blockIdx.y, t = threadIdx.x;
  for (int e = t; e < 6144; e += 256){
    int l = e / 512, rem = e % 512, w = rem >> 6, o = rem & 63;
    sm[e] = g_O[((size_t)(n * 12 + l) * 1024 + w0 + w) * 64 + o];
  }
  __syncthreads();
  for (int e = t; e < 6144; e += 256){
    int o = e / 96, rem = e % 96, w = rem / 12, l = rem % 12;
    out[((size_t)(n * 64 + o) * 1024 + w0 + w) * 12 + l] = sm[(l * 8 + w) * 64 + o];
  }
}

extern "C" void kernel_launch(void* const* d_in, const int* in_sizes, int n_in,
                              void* d_out, int out_size) {
  const float* x  = (const float*)d_in[0];
  const float* a0 = (const float*)d_in[1];
  const float* a1 = (const float*)d_in[2];
  const float* a2 = (const float*)d_in[3];
  const float* W  = (const float*)d_in[4];
  const float* b  = (const float*)d_in[5];
  float* out = (float*)d_out;
  cudaFuncSetAttribute(gemm_k, cudaFuncAttributeMaxDynamicSharedMemorySize, GSMEM);
  pack_a_k<<<3072, 1024>>>(a0, a1, a2);
  pack_w_k<<<56, 256>>>(W);
  pack_x_k<<<4096, 256>>>(x);
  gemm_k<<<dim3(8, 8, 3), 256, GSMEM>>>(0);
  gemm_k<<<dim3(48, 192, 1), 256, GSMEM>>>(1);
  gemm3_k<<<6144, 256>>>(b);
  trans_k<<<dim3(128, 64), 256>>>(out);
}

// round 7
// speedup vs baseline: 1.0731x; 1.0140x over previous
#include <cuda_runtime.h>
#include <cstdint>

__device__ float g_X[25165824];     // [m=(n,l,c)][v]
__device__ float g_A[3145728];      // rounded a0,a1,a2
__device__ float g_Asq[3145728];    // rounded squares
__device__ float g_P[176160768];    // planes [cc][n][l][w], cc 0..223
__device__ float g_O[50331648];     // [m=(n,l,w)][o]
__device__ float g_Wt[14336];       // [k][o]

__device__ __forceinline__ float rna(float x){
  unsigned u; asm("cvt.rna.tf32.f32 %0, %1;" : "=r"(u) : "f"(x));
  return __uint_as_float(u);
}
__device__ __forceinline__ void cp16(float* s, const float* g){
  unsigned sa = (unsigned)__cvta_generic_to_shared(s);
  asm volatile("cp.async.cg.shared.global [%0], [%1], 16;\n" :: "r"(sa), "l"(g));
}
__device__ __forceinline__ void cpcommit(){ asm volatile("cp.async.commit_group;\n"); }
__device__ __forceinline__ void cpwait(){ asm volatile("cp.async.wait_group 0;\n"); }
__device__ __forceinline__ void mma8(float* d, const unsigned* a, const unsigned* b){
  asm volatile("mma.sync.aligned.m16n8k8.row.col.f32.tf32.tf32.f32 "
    "{%0,%1,%2,%3},{%4,%5,%6,%7},{%8,%9},{%0,%1,%2,%3};\n"
    : "+f"(d[0]), "+f"(d[1]), "+f"(d[2]), "+f"(d[3])
    : "r"(a[0]), "r"(a[1]), "r"(a[2]), "r"(a[3]), "r"(b[0]), "r"(b[1]));
}

__global__ void pack_a_k(const float* __restrict__ a0, const float* __restrict__ a1,
                         const float* __restrict__ a2){
  int i = blockIdx.x * 1024 + threadIdx.x;
  int z = i >> 20;
  const float* s = (z == 0) ? a0 : ((z == 1) ? a1 : a2);
  g_A[i] = rna(s[i & 1048575]);
}
__global__ void pack_w_k(const float* __restrict__ W){
  int i = blockIdx.x * 256 + threadIdx.x;
  if (i < 14336){ int k = i >> 6, o = i & 63; g_Wt[i] = rna(W[o * 224 + k]); }
}
// x[n][c][v][l] -> g_X[(n*12+l)*32+c][v] and plane c: g_P[c][n][l][v]
__global__ void pack_x_k(const float* __restrict__ x){
  __shared__ float sm[6656];
  int nc = blockIdx.x >> 1, h = blockIdx.x & 1, t = threadIdx.x;
  int n = nc >> 5, c = nc & 31;
  const float* src = x + (size_t)nc * 12288 + h * 6144;
  for (int i = t; i < 6144; i += 256) sm[(i / 12) * 13 + (i % 12)] = src[i];
  __syncthreads();
  for (int l = 0; l < 12; l++){
    float* d1 = g_X + ((size_t)((n * 12 + l) * 32 + c)) * 1024 + h * 512;
    float* d2 = g_P + ((size_t)((c * 64 + n) * 12 + l)) * 1024 + h * 512;
    for (int v = t; v < 512; v += 256){ float r = rna(sm[v * 13 + l]); d1[v] = r; d2[v] = r; }
  }
}

// K=1024 tf32 GEMM, CTA tile 128x128, 4 warps of 64x64, KTILE=32, 2 buffers.
// smem (floats): A[2][128*36] at 0, B[2][32*136] at 9216. 17920 fl = 71680 B
#define GSMEM 71680
__global__ __launch_bounds__(128, 2) void gemm_k(int mode){
  extern __shared__ float sm[];
  const int t = threadIdx.x, lane = t & 31, wid = t >> 5;
  const int bx = blockIdx.x, by = blockIdx.y, bz = blockIdx.z;
  const float *Ap, *Bp; float* Cp = nullptr; int kb = 0, w0 = 0;
  if (mode == 0){
    size_t zo = (size_t)bz << 20;
    Ap = g_A + zo + (size_t)by * 131072;
    Bp = g_A + zo + bx * 128;
    Cp = g_Asq + zo + (size_t)by * 131072 + bx * 128;
  } else {
    Ap = g_X + (size_t)by * 131072;
    kb = bx >> 3; w0 = (bx & 7) * 128;
    Bp = ((kb & 1) ? g_Asq : g_A) + ((size_t)(kb >> 1) << 20) + w0;
  }
  float acc[4][8][4];
  #pragma unroll
  for (int i = 0; i < 4; i++) for (int j = 0; j < 8; j++) for (int q = 0; q < 4; q++) acc[i][j][q] = 0.f;
  { // prologue buffer 0
    float* As = sm; float* Bs = sm + 9216;
    #pragma unroll
    for (int i = 0; i < 8; i++){
      int idx = t + i * 128; int r = idx >> 3, q = idx & 7;
      cp16(As + r * 36 + q * 4, Ap + (size_t)r * 1024 + q * 4);
    }
    #pragma unroll
    for (int i = 0; i < 8; i++){
      int idx = t + i * 128; int r = idx >> 5, q = idx & 31;
      cp16(Bs + r * 136 + q * 4, Bp + (size_t)r * 1024 + q * 4);
    }
    cpcommit();
  }
  const int wm = wid >> 1, wn = wid & 1, arow = wm * 64, bcol = wn * 64;
  for (int kt = 0; kt < 32; kt++){
    int b = kt & 1;
    cpwait();
    __syncthreads();
    if (kt < 31){
      float* As = sm + (b ^ 1) * 4608; float* Bs = sm + 9216 + (b ^ 1) * 4352;
      const float* Ag = Ap + (kt + 1) * 32;
      const float* Bg = Bp + (size_t)(kt + 1) * 32768;
      #pragma unroll
      for (int i = 0; i < 8; i++){
        int idx = t + i * 128; int r = idx >> 3, q = idx & 7;
        cp16(As + r * 36 + q * 4, Ag + (size_t)r * 1024 + q * 4);
      }
      #pragma unroll
      for (int i = 0; i < 8; i++){
        int idx = t + i * 128; int r = idx >> 5, q = idx & 31;
        cp16(Bs + r * 136 + q * 4, Bg + (size_t)r * 1024 + q * 4);
      }
      cpcommit();
    } else {
      cpcommit();
    }
    const float* As = sm + b * 4608; const float* Bs = sm + 9216 + b * 4352;
    #pragma unroll
    for (int ks = 0; ks < 4; ks++){
      unsigned af[4][4], bf[8][2];
      int kk = ks * 8 + (lane & 3), rr = lane >> 2;
      #pragma unroll
      for (int mf = 0; mf < 4; mf++){
        int r = arow + mf * 16 + rr;
        af[mf][0] = __float_as_uint(As[r * 36 + kk]);
        af[mf][1] = __float_as_uint(As[(r + 8) * 36 + kk]);
        af[mf][2] = __float_as_uint(As[r * 36 + kk + 4]);
        af[mf][3] = __float_as_uint(As[(r + 8) * 36 + kk + 4]);
      }
      #pragma unroll
      for (int nf = 0; nf < 8; nf++){
        int cc = bcol + nf * 8 + rr;
        bf[nf][0] = __float_as_uint(Bs[kk * 136 + cc]);
        bf[nf][1] = __float_as_uint(Bs[(kk + 4) * 136 + cc]);
      }
      #pragma unroll
      for (int mf = 0; mf < 4; mf++)
        #pragma unroll
        for (int nf = 0; nf < 8; nf++) mma8(acc[mf][nf], af[mf], bf[nf]);
    }
  }
  cpwait();
  if (mode == 0){
    #pragma unroll
    for (int mf = 0; mf < 4; mf++){
      int r = arow + mf * 16 + (lane >> 2);
      #pragma unroll
      for (int nf = 0; nf < 8; nf++){
        int cc = bcol + nf * 8 + (lane & 3) * 2;
        Cp[(size_t)r * 1024 + cc]           = rna(acc[mf][nf][0]);
        Cp[(size_t)r * 1024 + cc + 1]       = rna(acc[mf][nf][1]);
        Cp[(size_t)(r + 8) * 1024 + cc]     = rna(acc[mf][nf][2]);
        Cp[(size_t)(r + 8) * 1024 + cc + 1] = rna(acc[mf][nf][3]);
      }
    }
  } else {
    for (int ph = 0; ph < 2; ph++){
      __syncthreads();
      if (wm == ph){
        #pragma unroll
        for (int mf = 0; mf < 4; mf++){
          int r = mf * 16 + (lane >> 2);
          #pragma unroll
          for (int nf = 0; nf < 8; nf++){
            int cc = bcol + nf * 8 + (lane & 3) * 2;
            sm[r * 136 + cc]           = rna(acc[mf][nf][0]);
            sm[r * 136 + cc + 1]       = rna(acc[mf][nf][1]);
            sm[(r + 8) * 136 + cc]     = rna(acc[mf][nf][2]);
            sm[(r + 8) * 136 + cc + 1] = rna(acc[mf][nf][3]);
          }
        }
      }
      __syncthreads();
      int m0 = by * 128 + ph * 64;
      #pragma unroll
      for (int i = 0; i < 16; i++){
        int e = t + i * 128, rr = e >> 5, q = e & 31;
        int m = m0 + rr, n = m / 384, rem = m % 384, l = rem >> 5, c = rem & 31;
        int p = 32 + kb * 32 + c;
        float4 v = *(const float4*)&sm[rr * 136 + q * 4];
        *(float4*)(g_P + ((size_t)((p * 64 + n) * 12 + l)) * 1024 + w0 + q * 4) = v;
      }
    }
  }
}

// stage 3: O[m][o] = sum_k P[k][m]*Wt[k][o] + b[o], tiles 128m x 64o, K=224
__global__ __launch_bounds__(256) void gemm3_k(const float* __restrict__ bias){
  __shared__ float As[1088], Ws[512];
  const int t = threadIdx.x, lane = t & 31, wid = t >> 5;
  const size_t m0 = (size_t)blockIdx.x * 128;
  const int wm = wid >> 1, wn = wid & 1;
  float acc[2][4][4];
  #pragma unroll
  for (int i = 0; i < 2; i++) for (int j = 0; j < 4; j++) for (int q = 0; q < 4; q++) acc[i][j][q] = 0.f;
  for (int kt = 0; kt < 28; kt++){
    __syncthreads();
    { int r = t >> 5, q = t & 31;
      *(float4*)&As[r * 136 + q * 4] = *(const float4*)(g_P + (size_t)(kt * 8 + r) * 786432 + m0 + q * 4);
      if (t < 128) *(float4*)&Ws[(t >> 4) * 64 + (t & 15) * 4] = *(const float4*)(g_Wt + (kt * 8 + (t >> 4)) * 64 + (t & 15) * 4);
    }
    __syncthreads();
    unsigned af[2][4], bf[4][2];
    int k = lane & 3, rr = lane >> 2;
    #pragma unroll
    for (int mf = 0; mf < 2; mf++){
      int r = wm * 32 + mf * 16 + rr;
      af[mf][0] = __float_as_uint(As[k * 136 + r]);
      af[mf][1] = __float_as_uint(As[k * 136 + r + 8]);
      af[mf][2] = __float_as_uint(As[(k + 4) * 136 + r]);
      af[mf][3] = __float_as_uint(As[(k + 4) * 136 + r + 8]);
    }
    #pragma unroll
    for (int nf = 0; nf < 4; nf++){
      int n0 = wn * 32 + nf * 8 + rr;
      bf[nf][0] = __float_as_uint(Ws[k * 64 + n0]);
      bf[nf][1] = __float_as_uint(Ws[(k + 4) * 64 + n0]);
    }
    #pragma unroll
    for (int mf = 0; mf < 2; mf++) for (int nf = 0; nf < 4; nf++) mma8(acc[mf][nf], af[mf], bf[nf]);
  }
  #pragma unroll
  for (int mf = 0; mf < 2; mf++){
    size_t r = m0 + wm * 32 + mf * 16 + (lane >> 2);
    #pragma unroll
    for (int nf = 0; nf < 4; nf++){
      int o = wn * 32 + nf * 8 + (lane & 3) * 2;
      float b0 = __ldg(bias + o), b1 = __ldg(bias + o + 1);
      g_O[r * 64 + o]           = acc[mf][nf][0] + b0;
      g_O[r * 64 + o + 1]       = acc[mf][nf][1] + b1;
      g_O[(r + 8) * 64 + o]     = acc[mf][nf][2] + b0;
      g_O[(r + 8) * 64 + o + 1] = acc[mf][nf][3] + b1;
    }
  }
}

// O[(n,l,w)][o] -> out[n][o][w][l]
__global__ void trans_k(float* __restrict__ out){
  __shared__ float sm[6144];
  int w0 = blockIdx.x * 8, n = blockIdx.y, t = threadIdx.x;
  for (int e = t; e < 6144; e += 256){
    int l = e / 512, rem = e % 512, w = rem >> 6, o = rem & 63;
    sm[e] = g_O[((size_t)(n * 12 + l) * 1024 + w0 + w) * 64 + o];
  }
  __syncthreads();
  for (int e = t; e < 6144; e += 256){
    int o = e / 96, rem = e % 96, w = rem / 12, l = rem % 12;
    out[((size_t)(n * 64 + o) * 1024 + w0 + w) * 12 + l] = sm[(l * 8 + w) * 64 + o];
  }
}

extern "C" void kernel_launch(void* const* d_in, const int* in_sizes, int n_in,
                              void* d_out, int out_size) {
  const float* x  = (const float*)d_in[0];
  const float* a0 = (const float*)d_in[1];
  const float* a1 = (const float*)d_in[2];
  const float* a2 = (const float*)d_in[3];
  const float* W  = (const float*)d_in[4];
  const float* b  = (const float*)d_in[5];
  float* out = (float*)d_out;
  cudaFuncSetAttribute(gemm_k, cudaFuncAttributeMaxDynamicSharedMemorySize, GSMEM);
  pack_a_k<<<3072, 1024>>>(a0, a1, a2);
  pack_w_k<<<56, 256>>>(W);
  pack_x_k<<<4096, 256>>>(x);
  gemm_k<<<dim3(8, 8, 3), 128, GSMEM>>>(0);
  gemm_k<<<dim3(48, 192, 1), 128, GSMEM>>>(1);
  gemm3_k<<<6144, 256>>>(b);
  trans_k<<<dim3(128, 64), 256>>>(out);
}